// round 12
// baseline (speedup 1.0000x reference)
#include <cuda_runtime.h>
#include <cuda_bf16.h>

#define NUM_LEVELS 256

__global__ __launch_bounds__(256, 8)
void NeuralQuantizer_7507602833923_kernel(const float* __restrict__ x,
                                          const float* __restrict__ centers,
                                          float* __restrict__ out,
                                          int n4) {
    __shared__ float cen[NUM_LEVELS];
    // Stage the 256-entry codebook once per CTA (coalesced, 1 iteration).
    cen[threadIdx.x] = centers[threadIdx.x];
    __syncthreads();

    const float inv_step = 127.5f;   // (NUM_LEVELS-1)/2 for linspace(-1,1,256)

    int i = blockIdx.x * blockDim.x + threadIdx.x;
    if (i >= n4) return;

    float4 v = reinterpret_cast<const float4*>(x)[i];
    float4 r;

    float* vp = reinterpret_cast<float*>(&v);
    float* rp = reinterpret_cast<float*>(&r);

    #pragma unroll
    for (int j = 0; j < 4; ++j) {
        float xv = vp[j];
        // Analytic nearest-center candidate (centers are uniform in [-1,1]).
        float t = fmaf(xv, inv_step, inv_step);          // (x+1)*127.5
        int k = (int)floorf(t + 0.5f);
        k = max(0, min(NUM_LEVELS - 1, k));

        // Exact argmin tie-break correction against the real center values:
        // jnp.argmin picks the LOWEST index on ties, distances computed in fp32.
        float dk = fabsf(xv - cen[k]);
        if (k > 0) {
            float dm = fabsf(xv - cen[k - 1]);
            if (dm <= dk) { k -= 1; dk = dm; }
        }
        if (k < NUM_LEVELS - 1) {
            float dp = fabsf(xv - cen[k + 1]);
            if (dp < dk) { k += 1; }
        }
        // Forward value of the straight-through estimator is just centers[k].
        rp[j] = cen[k];
    }

    reinterpret_cast<float4*>(out)[i] = r;
}

extern "C" void kernel_launch(void* const* d_in, const int* in_sizes, int n_in,
                              void* d_out, int out_size) {
    const float* x       = (const float*)d_in[0];
    const float* centers = (const float*)d_in[1];
    float* out           = (float*)d_out;

    int n = in_sizes[0];          // 2,097,152 — divisible by 4
    int n4 = n / 4;               // 524,288 float4 vectors

    int threads = 256;
    int blocks = (n4 + threads - 1) / threads;   // 2048
    NeuralQuantizer_7507602833923_kernel<<<blocks, threads>>>(x, centers, out, n4);
}